// round 14
// baseline (speedup 1.0000x reference)
#include <cuda_runtime.h>
#include <cuda_fp16.h>
#include <stdint.h>
#include <math.h>

// Problem constants
#define BATCH   16
#define NSEQ    784
#define DMODEL  512
#define NHEAD   8
#define DHEAD   64
#define BH      (BATCH * NHEAD)      // 128
#define MROWS   (BATCH * NSEQ)       // 12544
#define KPAIRS  256                  // 512/2

#define LOG2E   1.44269504f
#define QSCALE  0.18033688f          // 0.125 * log2(e)

// ---------------------------------------------------------------------------
// Scratch (device globals) — packed fp16 pairs stored as u32
// ---------------------------------------------------------------------------
__device__ uint32_t g_xq [MROWS * KPAIRS];    // queries fp16 [row][kp]
__device__ uint32_t g_xk [MROWS * KPAIRS];    // keys
__device__ uint32_t g_xv [MROWS * KPAIRS];    // values
__device__ uint32_t g_wq [DMODEL * KPAIRS];   // weights in B layout [n][kp]
__device__ uint32_t g_wk [DMODEL * KPAIRS];
__device__ uint32_t g_wv [DMODEL * KPAIRS];
__device__ uint32_t g_wo [DMODEL * KPAIRS];
__device__ float    g_bq [DMODEL];
__device__ float    g_bk [DMODEL];
__device__ float    g_bv [DMODEL];

__device__ uint32_t g_q  [BH * NSEQ * 32];    // q proj [bh][n][d/2] (pre-scaled)
__device__ uint32_t g_k  [BH * NSEQ * 32];    // k proj
__device__ uint32_t g_v  [BH * DHEAD * 392];  // v proj transposed [bh][d][n/2]
__device__ uint32_t g_ctx[MROWS * KPAIRS];    // attention output [row][kp]

// ---------------------------------------------------------------------------
// Helpers
// ---------------------------------------------------------------------------
__device__ __forceinline__ uint32_t pack2(float x0, float x1) {
    uint32_t r;   // x0 -> low half, x1 -> high half
    asm("cvt.rn.f16x2.f32 %0, %1, %2;" : "=r"(r) : "f"(x1), "f"(x0));
    return r;
}

__device__ __forceinline__ float ex2f(float x) {
    float r;
    asm("ex2.approx.f32 %0, %1;" : "=f"(r) : "f"(x));
    return r;
}

__device__ __forceinline__ void mma16816(float c[4], const uint32_t a[4],
                                         uint32_t b0, uint32_t b1) {
    asm volatile(
        "mma.sync.aligned.m16n8k16.row.col.f32.f16.f16.f32 "
        "{%0,%1,%2,%3}, {%4,%5,%6,%7}, {%8,%9}, {%0,%1,%2,%3};"
        : "+f"(c[0]), "+f"(c[1]), "+f"(c[2]), "+f"(c[3])
        : "r"(a[0]), "r"(a[1]), "r"(a[2]), "r"(a[3]), "r"(b0), "r"(b1));
}

__device__ __forceinline__ void ldsm_x4(uint32_t& r0, uint32_t& r1,
                                        uint32_t& r2, uint32_t& r3, uint32_t addr) {
    asm volatile("ldmatrix.sync.aligned.m8n8.x4.shared.b16 {%0,%1,%2,%3}, [%4];"
                 : "=r"(r0), "=r"(r1), "=r"(r2), "=r"(r3) : "r"(addr));
}

__device__ __forceinline__ uint32_t smem_u32addr(const void* p) {
    return (uint32_t)__cvta_generic_to_shared(p);
}

__device__ __forceinline__ void cp16(uint32_t dst, const void* src, uint32_t srcsize) {
    asm volatile("cp.async.cg.shared.global [%0], [%1], 16, %2;"
                 :: "r"(dst), "l"(src), "r"(srcsize) : "memory");
}
__device__ __forceinline__ void cp_commit() {
    asm volatile("cp.async.commit_group;" ::: "memory");
}
__device__ __forceinline__ void cp_wait1() {
    asm volatile("cp.async.wait_group 1;" ::: "memory");
}
__device__ __forceinline__ void cp_wait0() {
    asm volatile("cp.async.wait_group 0;" ::: "memory");
}

// ---------------------------------------------------------------------------
// Prep: fp32 -> packed fp16 pairs (+ stash QKV biases for the fused kernel)
// ---------------------------------------------------------------------------
__global__ __launch_bounds__(256) void convA(
    const float* __restrict__ Q, const float* __restrict__ K,
    const float* __restrict__ V,
    const float* __restrict__ bq, const float* __restrict__ bk,
    const float* __restrict__ bv)
{
    int idx = blockIdx.x * 256 + threadIdx.x;   // over MROWS*KPAIRS
    float2 a = reinterpret_cast<const float2*>(Q)[idx];
    g_xq[idx] = pack2(a.x, a.y);
    float2 b = reinterpret_cast<const float2*>(K)[idx];
    g_xk[idx] = pack2(b.x, b.y);
    float2 c = reinterpret_cast<const float2*>(V)[idx];
    g_xv[idx] = pack2(c.x, c.y);
    if (idx < DMODEL) {
        g_bq[idx] = bq[idx];
        g_bk[idx] = bk[idx];
        g_bv[idx] = bv[idx];
    }
}

__global__ __launch_bounds__(256) void convW(
    const float* __restrict__ Wq, const float* __restrict__ Wk,
    const float* __restrict__ Wv, const float* __restrict__ Wo)
{
    int which = blockIdx.x >> 9;
    int idx = (blockIdx.x & 511) * 256 + threadIdx.x;   // 0..131071
    int n  = idx & 511;
    int kp = idx >> 9;
    const float* W = (which == 0) ? Wq : (which == 1) ? Wk : (which == 2) ? Wv : Wo;
    uint32_t* dst  = (which == 0) ? g_wq : (which == 1) ? g_wk : (which == 2) ? g_wv : g_wo;
    float w0 = W[(2 * kp) * DMODEL + n];
    float w1 = W[(2 * kp + 1) * DMODEL + n];
    dst[n * KPAIRS + kp] = pack2(w0, w1);
}

// ---------------------------------------------------------------------------
// 3-stage pipelined GEMM core, tile 128x128, Kc=32, 256 threads.
// ---------------------------------------------------------------------------
#define GEMM_SMEM_BYTES 61440

// ---------------------------------------------------------------------------
// Fused QKV projection GEMM: one launch, blockIdx.z = which (0=q,1=k,2=v).
// q output is pre-scaled by QSCALE = 0.125*log2(e) for the exp2 softmax path.
// ---------------------------------------------------------------------------
__global__ __launch_bounds__(256) void gemm_qkv(void)
{
    extern __shared__ uint32_t sm[];   // [3][5120]: A @ s*5120, B @ s*5120+2560

    const int which = blockIdx.z;
    const uint32_t* Ag = (which == 0) ? g_xq : (which == 1) ? g_xk : g_xv;
    const uint32_t* Bg = (which == 0) ? g_wq : (which == 1) ? g_wk : g_wv;
    const float*  bias = (which == 0) ? g_bq : (which == 1) ? g_bk : g_bv;

    const int tid  = threadIdx.x;
    const int warp = tid >> 5;
    const int lane = tid & 31;
    const int g    = lane >> 2;
    const int qp   = lane & 3;
    const int row0 = blockIdx.x * 128;
    const int col0 = blockIdx.y * 128;

    const uint32_t s_sa = smem_u32addr(sm);

    // ldmatrix lane address offsets (bytes) within a stage
    const uint32_t a_lane = ((warp * 16 + (lane & 15)) * 20 + (lane >> 4) * 4) * 4;
    const uint32_t b_lane = 2560 * 4 +
        ((((lane >> 4) * 8) + (lane & 7)) * 20 + ((lane >> 3) & 1) * 4) * 4;

    auto load_chunk = [&](int c, int s) {
        const int cb = c * 16;
        const uint32_t base = s_sa + s * 5120 * 4;
#pragma unroll
        for (int i = tid; i < 512; i += 256) {
            int r = i >> 2, g4 = i & 3;
            cp16(base + (r * 20 + g4 * 4) * 4,
                 Ag + (size_t)(row0 + r) * KPAIRS + cb + g4 * 4, 16);
        }
#pragma unroll
        for (int i = tid; i < 512; i += 256) {
            int r = i >> 2, g4 = i & 3;
            cp16(base + 2560 * 4 + (r * 20 + g4 * 4) * 4,
                 Bg + (size_t)(col0 + r) * KPAIRS + cb + g4 * 4, 16);
        }
    };

    float C[16][4];
#pragma unroll
    for (int nt = 0; nt < 16; nt++)
#pragma unroll
        for (int i = 0; i < 4; i++) C[nt][i] = 0.f;

    load_chunk(0, 0); cp_commit();
    load_chunk(1, 1); cp_commit();

    for (int c = 0; c < 16; c++) {
        const int s = c % 3;
        if (c < 15) cp_wait1(); else cp_wait0();
        __syncthreads();
        if (c < 14) { load_chunk(c + 2, (c + 2) % 3); cp_commit(); }

        const uint32_t a_base = s_sa + s * 5120 * 4 + a_lane;
        const uint32_t b_base = s_sa + s * 5120 * 4 + b_lane;

#pragma unroll
        for (int t = 0; t < 2; t++) {
            uint32_t a[4];
            ldsm_x4(a[0], a[1], a[2], a[3], a_base + t * 32);
#pragma unroll
            for (int ntp = 0; ntp < 8; ntp++) {
                uint32_t b0, b1, b2, b3;
                ldsm_x4(b0, b1, b2, b3, b_base + ntp * 1280 + t * 32);
                mma16816(C[2 * ntp],     a, b0, b1);
                mma16816(C[2 * ntp + 1], a, b2, b3);
            }
        }
    }

    // ---- Epilogue ----
    const int rA = row0 + warp * 16 + g;
    const int rB = rA + 8;
    const int bA = rA / NSEQ, nA = rA % NSEQ;
    const int bB = rB / NSEQ, nB = rB % NSEQ;

    if (which != 2) {
        uint32_t* dst = (which == 0) ? g_q : g_k;
        const float sc = (which == 0) ? QSCALE : 1.f;
#pragma unroll
        for (int nt = 0; nt < 16; nt++) {
            int col = col0 + nt * 8 + 2 * qp;
            float2 bz = *reinterpret_cast<const float2*>(&bias[col]);
            int hh = col >> 6, dd = col & 63;
            dst[((size_t)(bA * NHEAD + hh) * NSEQ + nA) * 32 + (dd >> 1)] =
                pack2((C[nt][0] + bz.x) * sc, (C[nt][1] + bz.y) * sc);
            dst[((size_t)(bB * NHEAD + hh) * NSEQ + nB) * 32 + (dd >> 1)] =
                pack2((C[nt][2] + bz.x) * sc, (C[nt][3] + bz.y) * sc);
        }
    } else {
        // v: stage fp16 tile [128 c][136 n] then coalesced transposed store
        __half* Sh = reinterpret_cast<__half*>(sm);
        const int rlA = warp * 16 + g, rlB = rlA + 8;
        __syncthreads();
#pragma unroll
        for (int nt = 0; nt < 16; nt++) {
            int cl = nt * 8 + 2 * qp;
            float2 bz = *reinterpret_cast<const float2*>(&bias[col0 + cl]);
            Sh[cl * 136 + rlA]       = __float2half(C[nt][0] + bz.x);
            Sh[(cl + 1) * 136 + rlA] = __float2half(C[nt][1] + bz.y);
            Sh[cl * 136 + rlB]       = __float2half(C[nt][2] + bz.x);
            Sh[(cl + 1) * 136 + rlB] = __float2half(C[nt][3] + bz.y);
        }
        __syncthreads();
#pragma unroll
        for (int i = tid; i < 128 * 64; i += 256) {
            int cl = i >> 6;          // local col 0..127
            int np = i & 63;          // n-pair
            uint32_t val = *reinterpret_cast<const uint32_t*>(&Sh[cl * 136 + 2 * np]);
            int row = row0 + 2 * np;
            int b = row / NSEQ, n = row % NSEQ;
            int hh = (col0 >> 6) + (cl >> 6);
            int d  = cl & 63;
            g_v[((size_t)(b * NHEAD + hh) * DHEAD + d) * 392 + (n >> 1)] = val;
        }
    }
}

// ---------------------------------------------------------------------------
// Output projection GEMM: A=g_ctx -> out fp32 [b][c][n] (staged transpose)
// ---------------------------------------------------------------------------
__global__ __launch_bounds__(256) void gemm_out(
    const float* __restrict__ bias, float* __restrict__ out)
{
    extern __shared__ uint32_t sm[];

    const int tid  = threadIdx.x;
    const int warp = tid >> 5;
    const int lane = tid & 31;
    const int g    = lane >> 2;
    const int qp   = lane & 3;
    const int row0 = blockIdx.x * 128;
    const int col0 = blockIdx.y * 128;

    const uint32_t s_sa = smem_u32addr(sm);

    const uint32_t a_lane = ((warp * 16 + (lane & 15)) * 20 + (lane >> 4) * 4) * 4;
    const uint32_t b_lane = 2560 * 4 +
        ((((lane >> 4) * 8) + (lane & 7)) * 20 + ((lane >> 3) & 1) * 4) * 4;

    auto load_chunk = [&](int c, int s) {
        const int cb = c * 16;
        const uint32_t base = s_sa + s * 5120 * 4;
#pragma unroll
        for (int i = tid; i < 512; i += 256) {
            int r = i >> 2, g4 = i & 3;
            cp16(base + (r * 20 + g4 * 4) * 4,
                 g_ctx + (size_t)(row0 + r) * KPAIRS + cb + g4 * 4, 16);
        }
#pragma unroll
        for (int i = tid; i < 512; i += 256) {
            int r = i >> 2, g4 = i & 3;
            cp16(base + 2560 * 4 + (r * 20 + g4 * 4) * 4,
                 g_wo + (size_t)(col0 + r) * KPAIRS + cb + g4 * 4, 16);
        }
    };

    float C[16][4];
#pragma unroll
    for (int nt = 0; nt < 16; nt++)
#pragma unroll
        for (int i = 0; i < 4; i++) C[nt][i] = 0.f;

    load_chunk(0, 0); cp_commit();
    load_chunk(1, 1); cp_commit();

    for (int c = 0; c < 16; c++) {
        const int s = c % 3;
        if (c < 15) cp_wait1(); else cp_wait0();
        __syncthreads();
        if (c < 14) { load_chunk(c + 2, (c + 2) % 3); cp_commit(); }

        const uint32_t a_base = s_sa + s * 5120 * 4 + a_lane;
        const uint32_t b_base = s_sa + s * 5120 * 4 + b_lane;

#pragma unroll
        for (int t = 0; t < 2; t++) {
            uint32_t a[4];
            ldsm_x4(a[0], a[1], a[2], a[3], a_base + t * 32);
#pragma unroll
            for (int ntp = 0; ntp < 8; ntp++) {
                uint32_t b0, b1, b2, b3;
                ldsm_x4(b0, b1, b2, b3, b_base + ntp * 1280 + t * 32);
                mma16816(C[2 * ntp],     a, b0, b1);
                mma16816(C[2 * ntp + 1], a, b2, b3);
            }
        }
    }

    // two-pass smem-staged transpose epilogue
    float* Os = reinterpret_cast<float*>(sm);   // [64][132]
    const int rlA = warp * 16 + g, rlB = rlA + 8;
#pragma unroll
    for (int p = 0; p < 2; p++) {
        __syncthreads();
#pragma unroll
        for (int nt = p * 8; nt < p * 8 + 8; nt++) {
            int clp = (nt - p * 8) * 8 + 2 * qp;
            float2 bz = *reinterpret_cast<const float2*>(&bias[col0 + p * 64 + clp]);
            Os[clp * 132 + rlA]       = C[nt][0] + bz.x;
            Os[(clp + 1) * 132 + rlA] = C[nt][1] + bz.y;
            Os[clp * 132 + rlB]       = C[nt][2] + bz.x;
            Os[(clp + 1) * 132 + rlB] = C[nt][3] + bz.y;
        }
        __syncthreads();
#pragma unroll
        for (int i = tid; i < 64 * 128; i += 256) {
            int cc = i >> 7, nl = i & 127;
            int row = row0 + nl;
            int b = row / NSEQ, n = row % NSEQ;
            out[((size_t)(b * DMODEL + col0 + p * 64 + cc)) * NSEQ + n] =
                Os[cc * 132 + nl];
        }
    }
}

// ---------------------------------------------------------------------------
// Fused attention. Q pre-scaled by 0.125*log2e; p = ex2(fma(bias, log2e, s)).
// Row sums via ones-mma (B = fp16 1.0 constant). Mask only in tail tile.
// CTA = 64 q rows x (b,h), 128 threads. Writes ctx as packed fp16.
// ---------------------------------------------------------------------------
__global__ void __launch_bounds__(128, 4) attn_kernel(const float* __restrict__ self_corr)
{
    __shared__ uint32_t sm[11520];
    uint32_t* Qs  = sm;            // [64][36]
    uint32_t* KsB = sm + 2304;     // [2][64][36]
    uint32_t* VhB = sm + 6912;     // [2][64][36]

    const uint32_t ONES2 = 0x3C003C00u;   // fp16 {1.0, 1.0}

    const int tid  = threadIdx.x;
    const int warp = tid >> 5;
    const int lane = tid & 31;
    const int g    = lane >> 2;
    const int qp   = lane & 3;
    const int bh   = blockIdx.y;
    const int b    = bh >> 3, h = bh & 7;
    const int q0   = blockIdx.x * 64;

    const uint32_t* qg  = g_q + (size_t)bh * (NSEQ * 32);
    const uint32_t* kg  = g_k + (size_t)bh * (NSEQ * 32);
    const uint32_t* vhg = g_v + (size_t)bh * (DHEAD * 392);
    const float* biasb  = self_corr + (size_t)b * (NSEQ * NSEQ);

    const uint32_t qs_sa = smem_u32addr(Qs);
    const uint32_t ks_sa = smem_u32addr(KsB);
    const uint32_t vh_sa = smem_u32addr(VhB);

    // ldmatrix lane offsets (bytes), stride 36 u32 rows
    const uint32_t q_lane  = ((warp * 16 + (lane & 15)) * 36 + (lane >> 4) * 4) * 4;
    const uint32_t kv_lane = ((((lane >> 4) * 8) + (lane & 7)) * 36 + ((lane >> 3) & 1) * 4) * 4;

    auto load_tile = [&](int ti, int bi) {
        const int kt = ti * 64;
        uint32_t kd  = ks_sa + bi * 2304 * 4;
        uint32_t vhd = vh_sa + bi * 2304 * 4;
#pragma unroll
        for (int i = tid; i < 512; i += 128) {
            int r = i >> 3, g4 = i & 7;
            int kr = kt + r;
            uint32_t sz = (kr < NSEQ) ? 16u : 0u;
            int krc = kr < NSEQ ? kr : (NSEQ - 1);
            cp16(kd + (r * 36 + g4 * 4) * 4, kg + krc * 32 + g4 * 4, sz);
        }
#pragma unroll
        for (int i = tid; i < 512; i += 128) {
            int d = i >> 3, g4 = i & 7;
            int nc = kt + g4 * 8;
            uint32_t sz = (nc < NSEQ) ? 16u : 0u;
            int off = d * 392 + ((nc < NSEQ) ? ((kt >> 1) + g4 * 4) : 0);
            cp16(vhd + (d * 36 + g4 * 4) * 4, vhg + off, sz);
        }
    };

    // Stage Q tile, kick off tile 0 loads
#pragma unroll
    for (int j = 0; j < 16; j++) {
        int idx = tid + 128 * j;
        int r = idx >> 5, cw = idx & 31;
        int row = q0 + r; if (row > NSEQ - 1) row = NSEQ - 1;
        Qs[r * 36 + cw] = qg[row * 32 + cw];
    }
    load_tile(0, 0); cp_commit();
    __syncthreads();

    uint32_t QF[4][4];
#pragma unroll
    for (int t = 0; t < 4; t++)
        ldsm_x4(QF[t][0], QF[t][1], QF[t][2], QF[t][3], qs_sa + q_lane + t * 32);

    float O[8][4];
#pragma unroll
    for (int nt = 0; nt < 8; nt++)
#pragma unroll
        for (int i = 0; i < 4; i++) O[nt][i] = 0.f;
    float Osum[4] = {0.f, 0.f, 0.f, 0.f};

    const int rbias0 = min(q0 + warp * 16 + g, NSEQ - 1) * NSEQ;
    const int rbias1 = min(q0 + warp * 16 + g + 8, NSEQ - 1) * NSEQ;

    for (int ti = 0; ti < 13; ti++) {
        const int bi = ti & 1;
        const int kt = ti * 64;
        cp_wait0();
        __syncthreads();
        if (ti < 12) { load_tile(ti + 1, bi ^ 1); cp_commit(); }

        const uint32_t ks_base = ks_sa + bi * 2304 * 4 + kv_lane;
        const uint32_t vh_base = vh_sa + bi * 2304 * 4 + kv_lane;

        // S = Q' K^T  (Q pre-scaled by 0.125*log2e)
        float S[8][4];
#pragma unroll
        for (int nt = 0; nt < 8; nt++)
#pragma unroll
            for (int i = 0; i < 4; i++) S[nt][i] = 0.f;
#pragma unroll
        for (int ntp = 0; ntp < 4; ntp++) {
#pragma unroll
            for (int t = 0; t < 4; t++) {
                uint32_t b0, b1, b2, b3;
                ldsm_x4(b0, b1, b2, b3, ks_base + ntp * (16 * 36 * 4) + t * 32);
                mma16816(S[2 * ntp],     QF[t], b0, b1);
                mma16816(S[2 * ntp + 1], QF[t], b2, b3);
            }
        }

        // P = exp2(s + bias*log2e).  Mask only in the tail tile.
        if (ti < 12) {
#pragma unroll
            for (int nt = 0; nt < 8; nt++) {
                int colg = kt + nt * 8 + 2 * qp;
                float2 bA = *reinterpret_cast<const float2*>(&biasb[rbias0 + colg]);
                float2 bB = *reinterpret_cast<const float2*>(&biasb[rbias1 + colg]);
                S[nt][0] = ex2f(fmaf(bA.x, LOG2E, S[nt][0]));
                S[nt][1] = ex2f(fmaf(bA.y, LOG2E, S[nt][1]));
                S[nt][2] = ex2f(fmaf(bB.x, LOG2E, S[nt][2]));
                S[nt][3] = ex2f(fmaf(bB.y, LOG2E, S[nt][3]));
            }
        } else {
#pragma unroll
            for (int nt = 0; nt < 8; nt++) {
                int colg = kt + nt * 8 + 2 * qp;
                int colc = min(colg, NSEQ - 2);
                float2 bA = *reinterpret_cast<const float2*>(&biasb[rbias0 + colc]);
                float2 bB = *reinterpret_cast<const float2*>(&biasb[rbias1 + colc]);
                float p0 = ex2f(fmaf(bA.x, LOG2E, S[nt][0]));
                float p1 = ex2f(fmaf(bA.y, LOG2E, S[nt][1]));
                float p2 = ex2f(fmaf(bB.x, LOG2E, S[nt][2]));
                float p3 = ex2f(fmaf(bB.y, LOG2E, S[nt][3]));
                if (colg >= NSEQ)     { p0 = 0.f; p2 = 0.f; }
                if (colg + 1 >= NSEQ) { p1 = 0.f; p3 = 0.f; }
                S[nt][0] = p0; S[nt][1] = p1; S[nt][2] = p2; S[nt][3] = p3;
            }
        }

        // O += P @ V; row sums via ones-mma.
#pragma unroll
        for (int t = 0; t < 4; t++) {
            uint32_t PH[4];
            PH[0] = pack2(S[2 * t][0],     S[2 * t][1]);
            PH[1] = pack2(S[2 * t][2],     S[2 * t][3]);
            PH[2] = pack2(S[2 * t + 1][0], S[2 * t + 1][1]);
            PH[3] = pack2(S[2 * t + 1][2], S[2 * t + 1][3]);
            mma16816(Osum, PH, ONES2, ONES2);
#pragma unroll
            for (int ntp = 0; ntp < 4; ntp++) {
                uint32_t b0, b1, b2, b3;
                ldsm_x4(b0, b1, b2, b3, vh_base + ntp * (16 * 36 * 4) + t * 32);
                mma16816(O[2 * ntp],     PH, b0, b1);
                mma16816(O[2 * ntp + 1], PH, b2, b3);
            }
        }
    }

    // Normalize by mma row sums, write ctx as packed fp16 [row][kp]
    float inv0 = 1.f / Osum[0], inv1 = 1.f / Osum[2];
    int n0 = q0 + warp * 16 + g, n1 = n0 + 8;
#pragma unroll
    for (int nt = 0; nt < 8; nt++) {
        int kp = h * 32 + nt * 4 + qp;
        if (n0 < NSEQ)
            g_ctx[((size_t)b * NSEQ + n0) * KPAIRS + kp] =
                pack2(O[nt][0] * inv0, O[nt][1] * inv0);
        if (n1 < NSEQ)
            g_ctx[((size_t)b * NSEQ + n1) * KPAIRS + kp] =
                pack2(O[nt][2] * inv1, O[nt][3] * inv1);
    }
}

// ---------------------------------------------------------------------------
extern "C" void kernel_launch(void* const* d_in, const int* in_sizes, int n_in,
                              void* d_out, int out_size)
{
    const float* queries   = (const float*)d_in[0];
    const float* keys      = (const float*)d_in[1];
    const float* values    = (const float*)d_in[2];
    const float* self_corr = (const float*)d_in[3];
    const float* Wq = (const float*)d_in[4];
    const float* bq = (const float*)d_in[5];
    const float* Wk = (const float*)d_in[6];
    const float* bk = (const float*)d_in[7];
    const float* Wv = (const float*)d_in[8];
    const float* bv = (const float*)d_in[9];
    const float* Wo = (const float*)d_in[10];
    const float* bo = (const float*)d_in[11];
    float* out = (float*)d_out;

    cudaFuncSetAttribute(gemm_qkv, cudaFuncAttributeMaxDynamicSharedMemorySize,
                         GEMM_SMEM_BYTES);
    cudaFuncSetAttribute(gemm_out, cudaFuncAttributeMaxDynamicSharedMemorySize,
                         GEMM_SMEM_BYTES);

    convA<<<MROWS, 256>>>(queries, keys, values, bq, bk, bv);
    convW<<<2048, 256>>>(Wq, Wk, Wv, Wo);

    gemm_qkv<<<dim3(MROWS / 128, DMODEL / 128, 3), 256, GEMM_SMEM_BYTES>>>();

    attn_kernel<<<dim3(13, BH), 128>>>(self_corr);

    gemm_out<<<dim3(MROWS / 128, DMODEL / 128), 256, GEMM_SMEM_BYTES>>>(bo, out);
}

// round 15
// speedup vs baseline: 1.0393x; 1.0393x over previous
#include <cuda_runtime.h>
#include <cuda_fp16.h>
#include <stdint.h>
#include <math.h>

// Problem constants
#define BATCH   16
#define NSEQ    784
#define DMODEL  512
#define NHEAD   8
#define DHEAD   64
#define BH      (BATCH * NHEAD)      // 128
#define MROWS   (BATCH * NSEQ)       // 12544
#define KPAIRS  256                  // 512/2

#define LOG2E   1.44269504f
#define QSCALE  0.18033688f          // 0.125 * log2(e)

// ---------------------------------------------------------------------------
// Scratch (device globals) — packed fp16 pairs stored as u32
// ---------------------------------------------------------------------------
__device__ uint32_t g_xq [MROWS * KPAIRS];    // queries fp16 [row][kp]
__device__ uint32_t g_xk [MROWS * KPAIRS];    // keys
__device__ uint32_t g_xv [MROWS * KPAIRS];    // values
__device__ uint32_t g_wq [DMODEL * KPAIRS];   // weights in B layout [n][kp]
__device__ uint32_t g_wk [DMODEL * KPAIRS];
__device__ uint32_t g_wv [DMODEL * KPAIRS];
__device__ uint32_t g_wo [DMODEL * KPAIRS];
__device__ float    g_bq [DMODEL];
__device__ float    g_bk [DMODEL];
__device__ float    g_bv [DMODEL];

__device__ uint32_t g_q  [BH * NSEQ * 32];    // q proj [bh][n][d/2] (pre-scaled)
__device__ uint32_t g_k  [BH * NSEQ * 32];    // k proj
__device__ uint32_t g_v  [BH * DHEAD * 392];  // v proj transposed [bh][d][n/2]
__device__ uint32_t g_ctx[MROWS * KPAIRS];    // attention output [row][kp]

// ---------------------------------------------------------------------------
// Helpers
// ---------------------------------------------------------------------------
__device__ __forceinline__ uint32_t pack2(float x0, float x1) {
    uint32_t r;   // x0 -> low half, x1 -> high half
    asm("cvt.rn.f16x2.f32 %0, %1, %2;" : "=r"(r) : "f"(x1), "f"(x0));
    return r;
}

__device__ __forceinline__ float ex2f(float x) {
    float r;
    asm("ex2.approx.f32 %0, %1;" : "=f"(r) : "f"(x));
    return r;
}

__device__ __forceinline__ void mma16816(float c[4], const uint32_t a[4],
                                         uint32_t b0, uint32_t b1) {
    asm volatile(
        "mma.sync.aligned.m16n8k16.row.col.f32.f16.f16.f32 "
        "{%0,%1,%2,%3}, {%4,%5,%6,%7}, {%8,%9}, {%0,%1,%2,%3};"
        : "+f"(c[0]), "+f"(c[1]), "+f"(c[2]), "+f"(c[3])
        : "r"(a[0]), "r"(a[1]), "r"(a[2]), "r"(a[3]), "r"(b0), "r"(b1));
}

__device__ __forceinline__ void ldsm_x4(uint32_t& r0, uint32_t& r1,
                                        uint32_t& r2, uint32_t& r3, uint32_t addr) {
    asm volatile("ldmatrix.sync.aligned.m8n8.x4.shared.b16 {%0,%1,%2,%3}, [%4];"
                 : "=r"(r0), "=r"(r1), "=r"(r2), "=r"(r3) : "r"(addr));
}

__device__ __forceinline__ uint32_t smem_u32addr(const void* p) {
    return (uint32_t)__cvta_generic_to_shared(p);
}

__device__ __forceinline__ void cp16(uint32_t dst, const void* src, uint32_t srcsize) {
    asm volatile("cp.async.cg.shared.global [%0], [%1], 16, %2;"
                 :: "r"(dst), "l"(src), "r"(srcsize) : "memory");
}
__device__ __forceinline__ void cp_commit() {
    asm volatile("cp.async.commit_group;" ::: "memory");
}
__device__ __forceinline__ void cp_wait1() {
    asm volatile("cp.async.wait_group 1;" ::: "memory");
}
__device__ __forceinline__ void cp_wait0() {
    asm volatile("cp.async.wait_group 0;" ::: "memory");
}

// ---------------------------------------------------------------------------
// Prep: fp32 -> packed fp16 pairs (+ stash QKV biases for the fused kernel)
// ---------------------------------------------------------------------------
__global__ __launch_bounds__(256) void convA(
    const float* __restrict__ Q, const float* __restrict__ K,
    const float* __restrict__ V,
    const float* __restrict__ bq, const float* __restrict__ bk,
    const float* __restrict__ bv)
{
    int idx = blockIdx.x * 256 + threadIdx.x;   // over MROWS*KPAIRS
    float2 a = reinterpret_cast<const float2*>(Q)[idx];
    g_xq[idx] = pack2(a.x, a.y);
    float2 b = reinterpret_cast<const float2*>(K)[idx];
    g_xk[idx] = pack2(b.x, b.y);
    float2 c = reinterpret_cast<const float2*>(V)[idx];
    g_xv[idx] = pack2(c.x, c.y);
    if (idx < DMODEL) {
        g_bq[idx] = bq[idx];
        g_bk[idx] = bk[idx];
        g_bv[idx] = bv[idx];
    }
}

__global__ __launch_bounds__(256) void convW(
    const float* __restrict__ Wq, const float* __restrict__ Wk,
    const float* __restrict__ Wv, const float* __restrict__ Wo)
{
    int which = blockIdx.x >> 9;
    int idx = (blockIdx.x & 511) * 256 + threadIdx.x;   // 0..131071
    int n  = idx & 511;
    int kp = idx >> 9;
    const float* W = (which == 0) ? Wq : (which == 1) ? Wk : (which == 2) ? Wv : Wo;
    uint32_t* dst  = (which == 0) ? g_wq : (which == 1) ? g_wk : (which == 2) ? g_wv : g_wo;
    float w0 = W[(2 * kp) * DMODEL + n];
    float w1 = W[(2 * kp + 1) * DMODEL + n];
    dst[n * KPAIRS + kp] = pack2(w0, w1);
}

// ---------------------------------------------------------------------------
// 3-stage pipelined GEMM core, tile 128x128, Kc=32, 256 threads.
// ---------------------------------------------------------------------------
#define GEMM_SMEM_BYTES 61440

// ---------------------------------------------------------------------------
// Fused QKV projection GEMM: one launch, blockIdx.z = which (0=q,1=k,2=v).
// q output is pre-scaled by QSCALE = 0.125*log2(e) for the exp2 softmax path.
// ---------------------------------------------------------------------------
__global__ __launch_bounds__(256) void gemm_qkv(void)
{
    extern __shared__ uint32_t sm[];   // [3][5120]: A @ s*5120, B @ s*5120+2560

    const int which = blockIdx.z;
    const uint32_t* Ag = (which == 0) ? g_xq : (which == 1) ? g_xk : g_xv;
    const uint32_t* Bg = (which == 0) ? g_wq : (which == 1) ? g_wk : g_wv;
    const float*  bias = (which == 0) ? g_bq : (which == 1) ? g_bk : g_bv;

    const int tid  = threadIdx.x;
    const int warp = tid >> 5;
    const int lane = tid & 31;
    const int g    = lane >> 2;
    const int qp   = lane & 3;
    const int row0 = blockIdx.x * 128;
    const int col0 = blockIdx.y * 128;

    const uint32_t s_sa = smem_u32addr(sm);

    // ldmatrix lane address offsets (bytes) within a stage
    const uint32_t a_lane = ((warp * 16 + (lane & 15)) * 20 + (lane >> 4) * 4) * 4;
    const uint32_t b_lane = 2560 * 4 +
        ((((lane >> 4) * 8) + (lane & 7)) * 20 + ((lane >> 3) & 1) * 4) * 4;

    auto load_chunk = [&](int c, int s) {
        const int cb = c * 16;
        const uint32_t base = s_sa + s * 5120 * 4;
#pragma unroll
        for (int i = tid; i < 512; i += 256) {
            int r = i >> 2, g4 = i & 3;
            cp16(base + (r * 20 + g4 * 4) * 4,
                 Ag + (size_t)(row0 + r) * KPAIRS + cb + g4 * 4, 16);
        }
#pragma unroll
        for (int i = tid; i < 512; i += 256) {
            int r = i >> 2, g4 = i & 3;
            cp16(base + 2560 * 4 + (r * 20 + g4 * 4) * 4,
                 Bg + (size_t)(col0 + r) * KPAIRS + cb + g4 * 4, 16);
        }
    };

    float C[16][4];
#pragma unroll
    for (int nt = 0; nt < 16; nt++)
#pragma unroll
        for (int i = 0; i < 4; i++) C[nt][i] = 0.f;

    load_chunk(0, 0); cp_commit();
    load_chunk(1, 1); cp_commit();

    for (int c = 0; c < 16; c++) {
        const int s = c % 3;
        if (c < 15) cp_wait1(); else cp_wait0();
        __syncthreads();
        if (c < 14) { load_chunk(c + 2, (c + 2) % 3); cp_commit(); }

        const uint32_t a_base = s_sa + s * 5120 * 4 + a_lane;
        const uint32_t b_base = s_sa + s * 5120 * 4 + b_lane;

#pragma unroll
        for (int t = 0; t < 2; t++) {
            uint32_t a[4];
            ldsm_x4(a[0], a[1], a[2], a[3], a_base + t * 32);
#pragma unroll
            for (int ntp = 0; ntp < 8; ntp++) {
                uint32_t b0, b1, b2, b3;
                ldsm_x4(b0, b1, b2, b3, b_base + ntp * 1280 + t * 32);
                mma16816(C[2 * ntp],     a, b0, b1);
                mma16816(C[2 * ntp + 1], a, b2, b3);
            }
        }
    }

    // ---- Epilogue ----
    const int rA = row0 + warp * 16 + g;
    const int rB = rA + 8;
    const int bA = rA / NSEQ, nA = rA % NSEQ;
    const int bB = rB / NSEQ, nB = rB % NSEQ;

    if (which != 2) {
        uint32_t* dst = (which == 0) ? g_q : g_k;
        const float sc = (which == 0) ? QSCALE : 1.f;
#pragma unroll
        for (int nt = 0; nt < 16; nt++) {
            int col = col0 + nt * 8 + 2 * qp;
            float2 bz = *reinterpret_cast<const float2*>(&bias[col]);
            int hh = col >> 6, dd = col & 63;
            dst[((size_t)(bA * NHEAD + hh) * NSEQ + nA) * 32 + (dd >> 1)] =
                pack2((C[nt][0] + bz.x) * sc, (C[nt][1] + bz.y) * sc);
            dst[((size_t)(bB * NHEAD + hh) * NSEQ + nB) * 32 + (dd >> 1)] =
                pack2((C[nt][2] + bz.x) * sc, (C[nt][3] + bz.y) * sc);
        }
    } else {
        // v: stage fp16 tile [128 c][136 n] then coalesced transposed store
        __half* Sh = reinterpret_cast<__half*>(sm);
        const int rlA = warp * 16 + g, rlB = rlA + 8;
        __syncthreads();
#pragma unroll
        for (int nt = 0; nt < 16; nt++) {
            int cl = nt * 8 + 2 * qp;
            float2 bz = *reinterpret_cast<const float2*>(&bias[col0 + cl]);
            Sh[cl * 136 + rlA]       = __float2half(C[nt][0] + bz.x);
            Sh[(cl + 1) * 136 + rlA] = __float2half(C[nt][1] + bz.y);
            Sh[cl * 136 + rlB]       = __float2half(C[nt][2] + bz.x);
            Sh[(cl + 1) * 136 + rlB] = __float2half(C[nt][3] + bz.y);
        }
        __syncthreads();
#pragma unroll
        for (int i = tid; i < 128 * 64; i += 256) {
            int cl = i >> 6;          // local col 0..127
            int np = i & 63;          // n-pair
            uint32_t val = *reinterpret_cast<const uint32_t*>(&Sh[cl * 136 + 2 * np]);
            int row = row0 + 2 * np;
            int b = row / NSEQ, n = row % NSEQ;
            int hh = (col0 >> 6) + (cl >> 6);
            int d  = cl & 63;
            g_v[((size_t)(b * NHEAD + hh) * DHEAD + d) * 392 + (n >> 1)] = val;
        }
    }
}

// ---------------------------------------------------------------------------
// Output projection GEMM: A=g_ctx -> out fp32 [b][c][n] (staged transpose)
// ---------------------------------------------------------------------------
__global__ __launch_bounds__(256) void gemm_out(
    const float* __restrict__ bias, float* __restrict__ out)
{
    extern __shared__ uint32_t sm[];

    const int tid  = threadIdx.x;
    const int warp = tid >> 5;
    const int lane = tid & 31;
    const int g    = lane >> 2;
    const int qp   = lane & 3;
    const int row0 = blockIdx.x * 128;
    const int col0 = blockIdx.y * 128;

    const uint32_t s_sa = smem_u32addr(sm);

    const uint32_t a_lane = ((warp * 16 + (lane & 15)) * 20 + (lane >> 4) * 4) * 4;
    const uint32_t b_lane = 2560 * 4 +
        ((((lane >> 4) * 8) + (lane & 7)) * 20 + ((lane >> 3) & 1) * 4) * 4;

    auto load_chunk = [&](int c, int s) {
        const int cb = c * 16;
        const uint32_t base = s_sa + s * 5120 * 4;
#pragma unroll
        for (int i = tid; i < 512; i += 256) {
            int r = i >> 2, g4 = i & 3;
            cp16(base + (r * 20 + g4 * 4) * 4,
                 g_ctx + (size_t)(row0 + r) * KPAIRS + cb + g4 * 4, 16);
        }
#pragma unroll
        for (int i = tid; i < 512; i += 256) {
            int r = i >> 2, g4 = i & 3;
            cp16(base + 2560 * 4 + (r * 20 + g4 * 4) * 4,
                 g_wo + (size_t)(col0 + r) * KPAIRS + cb + g4 * 4, 16);
        }
    };

    float C[16][4];
#pragma unroll
    for (int nt = 0; nt < 16; nt++)
#pragma unroll
        for (int i = 0; i < 4; i++) C[nt][i] = 0.f;

    load_chunk(0, 0); cp_commit();
    load_chunk(1, 1); cp_commit();

    for (int c = 0; c < 16; c++) {
        const int s = c % 3;
        if (c < 15) cp_wait1(); else cp_wait0();
        __syncthreads();
        if (c < 14) { load_chunk(c + 2, (c + 2) % 3); cp_commit(); }

        const uint32_t a_base = s_sa + s * 5120 * 4 + a_lane;
        const uint32_t b_base = s_sa + s * 5120 * 4 + b_lane;

#pragma unroll
        for (int t = 0; t < 2; t++) {
            uint32_t a[4];
            ldsm_x4(a[0], a[1], a[2], a[3], a_base + t * 32);
#pragma unroll
            for (int ntp = 0; ntp < 8; ntp++) {
                uint32_t b0, b1, b2, b3;
                ldsm_x4(b0, b1, b2, b3, b_base + ntp * 1280 + t * 32);
                mma16816(C[2 * ntp],     a, b0, b1);
                mma16816(C[2 * ntp + 1], a, b2, b3);
            }
        }
    }

    // two-pass smem-staged transpose epilogue
    float* Os = reinterpret_cast<float*>(sm);   // [64][132]
    const int rlA = warp * 16 + g, rlB = rlA + 8;
#pragma unroll
    for (int p = 0; p < 2; p++) {
        __syncthreads();
#pragma unroll
        for (int nt = p * 8; nt < p * 8 + 8; nt++) {
            int clp = (nt - p * 8) * 8 + 2 * qp;
            float2 bz = *reinterpret_cast<const float2*>(&bias[col0 + p * 64 + clp]);
            Os[clp * 132 + rlA]       = C[nt][0] + bz.x;
            Os[(clp + 1) * 132 + rlA] = C[nt][1] + bz.y;
            Os[clp * 132 + rlB]       = C[nt][2] + bz.x;
            Os[(clp + 1) * 132 + rlB] = C[nt][3] + bz.y;
        }
        __syncthreads();
#pragma unroll
        for (int i = tid; i < 64 * 128; i += 256) {
            int cc = i >> 7, nl = i & 127;
            int row = row0 + nl;
            int b = row / NSEQ, n = row % NSEQ;
            out[((size_t)(b * DMODEL + col0 + p * 64 + cc)) * NSEQ + n] =
                Os[cc * 132 + nl];
        }
    }
}

// ---------------------------------------------------------------------------
// Fused attention. Q pre-scaled by 0.125*log2e; p = ex2(fma(bias, log2e, s)).
// Row sums via independent FADDs + shfl (latency filler). Mask only in tail.
// CTA = 64 q rows x (b,h), 128 threads. Writes ctx as packed fp16.
// ---------------------------------------------------------------------------
__global__ void __launch_bounds__(128, 4) attn_kernel(const float* __restrict__ self_corr)
{
    __shared__ uint32_t sm[11520];
    uint32_t* Qs  = sm;            // [64][36]
    uint32_t* KsB = sm + 2304;     // [2][64][36]
    uint32_t* VhB = sm + 6912;     // [2][64][36]

    const int tid  = threadIdx.x;
    const int warp = tid >> 5;
    const int lane = tid & 31;
    const int g    = lane >> 2;
    const int qp   = lane & 3;
    const int bh   = blockIdx.y;
    const int b    = bh >> 3, h = bh & 7;
    const int q0   = blockIdx.x * 64;

    const uint32_t* qg  = g_q + (size_t)bh * (NSEQ * 32);
    const uint32_t* kg  = g_k + (size_t)bh * (NSEQ * 32);
    const uint32_t* vhg = g_v + (size_t)bh * (DHEAD * 392);
    const float* biasb  = self_corr + (size_t)b * (NSEQ * NSEQ);

    const uint32_t qs_sa = smem_u32addr(Qs);
    const uint32_t ks_sa = smem_u32addr(KsB);
    const uint32_t vh_sa = smem_u32addr(VhB);

    // ldmatrix lane offsets (bytes), stride 36 u32 rows
    const uint32_t q_lane  = ((warp * 16 + (lane & 15)) * 36 + (lane >> 4) * 4) * 4;
    const uint32_t kv_lane = ((((lane >> 4) * 8) + (lane & 7)) * 36 + ((lane >> 3) & 1) * 4) * 4;

    auto load_tile = [&](int ti, int bi) {
        const int kt = ti * 64;
        uint32_t kd  = ks_sa + bi * 2304 * 4;
        uint32_t vhd = vh_sa + bi * 2304 * 4;
#pragma unroll
        for (int i = tid; i < 512; i += 128) {
            int r = i >> 3, g4 = i & 7;
            int kr = kt + r;
            uint32_t sz = (kr < NSEQ) ? 16u : 0u;
            int krc = kr < NSEQ ? kr : (NSEQ - 1);
            cp16(kd + (r * 36 + g4 * 4) * 4, kg + krc * 32 + g4 * 4, sz);
        }
#pragma unroll
        for (int i = tid; i < 512; i += 128) {
            int d = i >> 3, g4 = i & 7;
            int nc = kt + g4 * 8;
            uint32_t sz = (nc < NSEQ) ? 16u : 0u;
            int off = d * 392 + ((nc < NSEQ) ? ((kt >> 1) + g4 * 4) : 0);
            cp16(vhd + (d * 36 + g4 * 4) * 4, vhg + off, sz);
        }
    };

    // Stage Q tile, kick off tile 0 loads
#pragma unroll
    for (int j = 0; j < 16; j++) {
        int idx = tid + 128 * j;
        int r = idx >> 5, cw = idx & 31;
        int row = q0 + r; if (row > NSEQ - 1) row = NSEQ - 1;
        Qs[r * 36 + cw] = qg[row * 32 + cw];
    }
    load_tile(0, 0); cp_commit();
    __syncthreads();

    uint32_t QF[4][4];
#pragma unroll
    for (int t = 0; t < 4; t++)
        ldsm_x4(QF[t][0], QF[t][1], QF[t][2], QF[t][3], qs_sa + q_lane + t * 32);

    float O[8][4];
#pragma unroll
    for (int nt = 0; nt < 8; nt++)
#pragma unroll
        for (int i = 0; i < 4; i++) O[nt][i] = 0.f;

    float l0 = 0.f, l1 = 0.f;
    const int rbias0 = min(q0 + warp * 16 + g, NSEQ - 1) * NSEQ;
    const int rbias1 = min(q0 + warp * 16 + g + 8, NSEQ - 1) * NSEQ;

    for (int ti = 0; ti < 13; ti++) {
        const int bi = ti & 1;
        const int kt = ti * 64;
        cp_wait0();
        __syncthreads();
        if (ti < 12) { load_tile(ti + 1, bi ^ 1); cp_commit(); }

        const uint32_t ks_base = ks_sa + bi * 2304 * 4 + kv_lane;
        const uint32_t vh_base = vh_sa + bi * 2304 * 4 + kv_lane;

        // S = Q' K^T  (Q pre-scaled by 0.125*log2e)
        float S[8][4];
#pragma unroll
        for (int nt = 0; nt < 8; nt++)
#pragma unroll
            for (int i = 0; i < 4; i++) S[nt][i] = 0.f;
#pragma unroll
        for (int ntp = 0; ntp < 4; ntp++) {
#pragma unroll
            for (int t = 0; t < 4; t++) {
                uint32_t b0, b1, b2, b3;
                ldsm_x4(b0, b1, b2, b3, ks_base + ntp * (16 * 36 * 4) + t * 32);
                mma16816(S[2 * ntp],     QF[t], b0, b1);
                mma16816(S[2 * ntp + 1], QF[t], b2, b3);
            }
        }

        // P = exp2(s + bias*log2e); row-sum partials. Mask only in tail tile.
        float ls0 = 0.f, ls1 = 0.f;
        if (ti < 12) {
#pragma unroll
            for (int nt = 0; nt < 8; nt++) {
                int colg = kt + nt * 8 + 2 * qp;
                float2 bA = *reinterpret_cast<const float2*>(&biasb[rbias0 + colg]);
                float2 bB = *reinterpret_cast<const float2*>(&biasb[rbias1 + colg]);
                float p0 = ex2f(fmaf(bA.x, LOG2E, S[nt][0]));
                float p1 = ex2f(fmaf(bA.y, LOG2E, S[nt][1]));
                float p2 = ex2f(fmaf(bB.x, LOG2E, S[nt][2]));
                float p3 = ex2f(fmaf(bB.y, LOG2E, S[nt][3]));
                S[nt][0] = p0; S[nt][1] = p1; S[nt][2] = p2; S[nt][3] = p3;
                ls0 += p0 + p1;
                ls1 += p2 + p3;
            }
        } else {
#pragma unroll
            for (int nt = 0; nt < 8; nt++) {
                int colg = kt + nt * 8 + 2 * qp;
                int colc = min(colg, NSEQ - 2);
                float2 bA = *reinterpret_cast<const float2*>(&biasb[rbias0 + colc]);
                float2 bB = *reinterpret_cast<const float2*>(&biasb[rbias1 + colc]);
                float p0 = ex2f(fmaf(bA.x, LOG2E, S[nt][0]));
                float p1 = ex2f(fmaf(bA.y, LOG2E, S[nt][1]));
                float p2 = ex2f(fmaf(bB.x, LOG2E, S[nt][2]));
                float p3 = ex2f(fmaf(bB.y, LOG2E, S[nt][3]));
                if (colg >= NSEQ)     { p0 = 0.f; p2 = 0.f; }
                if (colg + 1 >= NSEQ) { p1 = 0.f; p3 = 0.f; }
                S[nt][0] = p0; S[nt][1] = p1; S[nt][2] = p2; S[nt][3] = p3;
                ls0 += p0 + p1;
                ls1 += p2 + p3;
            }
        }
        l0 += ls0;
        l1 += ls1;

        // O += P @ V  (V frags via ldmatrix: rows = d, stride 36)
#pragma unroll
        for (int t = 0; t < 4; t++) {
            uint32_t PH[4];
            PH[0] = pack2(S[2 * t][0],     S[2 * t][1]);
            PH[1] = pack2(S[2 * t][2],     S[2 * t][3]);
            PH[2] = pack2(S[2 * t + 1][0], S[2 * t + 1][1]);
            PH[3] = pack2(S[2 * t + 1][2], S[2 * t + 1][3]);
#pragma unroll
            for (int ntp = 0; ntp < 4; ntp++) {
                uint32_t b0, b1, b2, b3;
                ldsm_x4(b0, b1, b2, b3, vh_base + ntp * (16 * 36 * 4) + t * 32);
                mma16816(O[2 * ntp],     PH, b0, b1);
                mma16816(O[2 * ntp + 1], PH, b2, b3);
            }
        }
    }

    // Row sums across the quad, normalize, write ctx as packed fp16 [row][kp]
    l0 += __shfl_xor_sync(0xffffffffu, l0, 1);
    l0 += __shfl_xor_sync(0xffffffffu, l0, 2);
    l1 += __shfl_xor_sync(0xffffffffu, l1, 1);
    l1 += __shfl_xor_sync(0xffffffffu, l1, 2);
    float inv0 = 1.f / l0, inv1 = 1.f / l1;
    int n0 = q0 + warp * 16 + g, n1 = n0 + 8;
#pragma unroll
    for (int nt = 0; nt < 8; nt++) {
        int kp = h * 32 + nt * 4 + qp;
        if (n0 < NSEQ)
            g_ctx[((size_t)b * NSEQ + n0) * KPAIRS + kp] =
                pack2(O[nt][0] * inv0, O[nt][1] * inv0);
        if (n1 < NSEQ)
            g_ctx[((size_t)b * NSEQ + n1) * KPAIRS + kp] =
                pack2(O[nt][2] * inv1, O[nt][3] * inv1);
    }
}

// ---------------------------------------------------------------------------
extern "C" void kernel_launch(void* const* d_in, const int* in_sizes, int n_in,
                              void* d_out, int out_size)
{
    const float* queries   = (const float*)d_in[0];
    const float* keys      = (const float*)d_in[1];
    const float* values    = (const float*)d_in[2];
    const float* self_corr = (const float*)d_in[3];
    const float* Wq = (const float*)d_in[4];
    const float* bq = (const float*)d_in[5];
    const float* Wk = (const float*)d_in[6];
    const float* bk = (const float*)d_in[7];
    const float* Wv = (const float*)d_in[8];
    const float* bv = (const float*)d_in[9];
    const float* Wo = (const float*)d_in[10];
    const float* bo = (const float*)d_in[11];
    float* out = (float*)d_out;

    cudaFuncSetAttribute(gemm_qkv, cudaFuncAttributeMaxDynamicSharedMemorySize,
                         GEMM_SMEM_BYTES);
    cudaFuncSetAttribute(gemm_out, cudaFuncAttributeMaxDynamicSharedMemorySize,
                         GEMM_SMEM_BYTES);

    convA<<<MROWS, 256>>>(queries, keys, values, bq, bk, bv);
    convW<<<2048, 256>>>(Wq, Wk, Wv, Wo);

    gemm_qkv<<<dim3(MROWS / 128, DMODEL / 128, 3), 256, GEMM_SMEM_BYTES>>>();

    attn_kernel<<<dim3(13, BH), 128>>>(self_corr);

    gemm_out<<<dim3(MROWS / 128, DMODEL / 128), 256, GEMM_SMEM_BYTES>>>(bo, out);
}